// round 1
// baseline (speedup 1.0000x reference)
#include <cuda_runtime.h>

typedef unsigned long long u64;

// ---- packed f32x2 helpers (Blackwell packed FP32 path; ptxas never auto-fuses) ----
__device__ __forceinline__ u64 pack2(float lo, float hi) {
    u64 r; asm("mov.b64 %0, {%1, %2};" : "=l"(r) : "f"(lo), "f"(hi)); return r;
}
__device__ __forceinline__ void unpack2(u64 v, float& lo, float& hi) {
    asm("mov.b64 {%0, %1}, %2;" : "=f"(lo), "=f"(hi) : "l"(v));
}
__device__ __forceinline__ u64 fma2(u64 a, u64 b, u64 c) {
    u64 d; asm("fma.rn.f32x2 %0, %1, %2, %3;" : "=l"(d) : "l"(a), "l"(b), "l"(c)); return d;
}

// ---- accurate fast transcendentals (MUFU EX2 ~2^-22 rel err, RCP ~1 ulp) ----
__device__ __forceinline__ float ex2f(float x) { float r; asm("ex2.approx.f32 %0, %1;" : "=f"(r) : "f"(x)); return r; }
__device__ __forceinline__ float rcpf(float x) { float r; asm("rcp.approx.f32 %0, %1;" : "=f"(r) : "f"(x)); return r; }
__device__ __forceinline__ float sigf(float x)  { return rcpf(1.0f + ex2f(-1.4426950408889634f * x)); }
__device__ __forceinline__ float tanhf_(float x) { return fmaf(-2.0f, rcpf(1.0f + ex2f(2.8853900817779268f * x)), 1.0f); }

#define TSTEPS 512
#define WARPS_PER_CTA 4

// One warp per batch row. Lane j owns hidden unit j.
// Gates packed as f32x2 pairs: (i,f) in a01, (g,o) in a23.
// h broadcast via SMEM: each lane stores {h,h} as u64, k-loop reads 32 broadcast LDS.64.
__global__ void __launch_bounds__(32 * WARPS_PER_CTA)
lstm_kernel(const float* __restrict__ x,
            const float* __restrict__ W_ih,
            const float* __restrict__ W_hh,
            const float* __restrict__ b_ih,
            const float* __restrict__ b_hh,
            const float* __restrict__ W_fc,
            const float* __restrict__ b_fc,
            float* __restrict__ out, int B)
{
    __shared__ u64 hbuf[WARPS_PER_CTA][32];
    const int wlocal = threadIdx.x >> 5;
    const int lane   = threadIdx.x & 31;
    const int b      = blockIdx.x * WARPS_PER_CTA + wlocal;
    if (b >= B) return;
    u64* hw = hbuf[wlocal];

    // ---- preload weights into registers (128 regs/lane for W_hh) ----
    u64 w01[32], w23[32];
#pragma unroll
    for (int k = 0; k < 32; k++) {
        w01[k] = pack2(W_hh[(0 * 32 + lane) * 32 + k], W_hh[(1 * 32 + lane) * 32 + k]);
        w23[k] = pack2(W_hh[(2 * 32 + lane) * 32 + k], W_hh[(3 * 32 + lane) * 32 + k]);
    }
    const u64 wih01  = pack2(W_ih[0 * 32 + lane], W_ih[1 * 32 + lane]);
    const u64 wih23  = pack2(W_ih[2 * 32 + lane], W_ih[3 * 32 + lane]);
    const u64 bias01 = pack2(b_ih[0 * 32 + lane] + b_hh[0 * 32 + lane],
                             b_ih[1 * 32 + lane] + b_hh[1 * 32 + lane]);
    const u64 bias23 = pack2(b_ih[2 * 32 + lane] + b_hh[2 * 32 + lane],
                             b_ih[3 * 32 + lane] + b_hh[3 * 32 + lane]);

    float h = 0.0f, c = 0.0f;
    hw[lane] = 0ull;
    __syncwarp();

    const float* xb = x + (size_t)b * TSTEPS;

#pragma unroll 1
    for (int tc = 0; tc < TSTEPS; tc += 32) {
        float xchunk = xb[tc + lane];  // coalesced 128B load per warp per 32 steps
#pragma unroll 1
        for (int tt = 0; tt < 32; tt++) {
            float xv = __shfl_sync(0xffffffffu, xchunk, tt);
            u64 xv2 = pack2(xv, xv);
            u64 a01 = fma2(xv2, wih01, bias01);
            u64 a23 = fma2(xv2, wih23, bias23);
#pragma unroll
            for (int k = 0; k < 32; k++) {
                u64 hk2 = hw[k];                 // broadcast LDS.64 {h[k], h[k]}
                a01 = fma2(w01[k], hk2, a01);
                a23 = fma2(w23[k], hk2, a23);
            }
            float ai, af, ag, ao;
            unpack2(a01, ai, af);
            unpack2(a23, ag, ao);
            float ig = sigf(ai);
            float fg = sigf(af);
            float gg = tanhf_(ag);
            float og = sigf(ao);
            c = fmaf(fg, c, ig * gg);
            h = og * tanhf_(c);
            __syncwarp();                 // all lanes done reading old h
            hw[lane] = pack2(h, h);
            __syncwarp();                 // new h visible before next step's reads
        }
    }

    // ---- final head: out[b] = dot(h, W_fc) + b_fc ----
    float p = h * W_fc[lane];
#pragma unroll
    for (int off = 16; off; off >>= 1)
        p += __shfl_xor_sync(0xffffffffu, p, off);
    if (lane == 0) out[b] = p + b_fc[0];
}

extern "C" void kernel_launch(void* const* d_in, const int* in_sizes, int n_in,
                              void* d_out, int out_size)
{
    const float* x    = (const float*)d_in[0];
    const float* W_ih = (const float*)d_in[1];
    const float* W_hh = (const float*)d_in[2];
    const float* b_ih = (const float*)d_in[3];
    const float* b_hh = (const float*)d_in[4];
    const float* W_fc = (const float*)d_in[5];
    const float* b_fc = (const float*)d_in[6];
    float* out = (float*)d_out;

    int B = in_sizes[0] / TSTEPS;  // x is [B, 512, 1]
    int blocks = (B + WARPS_PER_CTA - 1) / WARPS_PER_CTA;
    lstm_kernel<<<blocks, 32 * WARPS_PER_CTA>>>(x, W_ih, W_hh, b_ih, b_hh, W_fc, b_fc, out, B);
}